// round 15
// baseline (speedup 1.0000x reference)
#include <cuda_runtime.h>
#include <math.h>

#define B_    32
#define L_    64
#define D_    768
#define LL_   (L_*L_)     // 4096
#define OUTD_ (2*D_)      // 1536
#define D4_   (D_/4)      // 192
#define GRIDF_ 192

// scratch (monotonic barrier counter -> graph-replay-safe)
__device__ float    g_pooled[B_ * D_];
__device__ unsigned g_bar[2];

__device__ __forceinline__ void gsync(int i)
{
    __syncthreads();
    if (threadIdx.x == 0) {
        __threadfence();
        unsigned v = atomicAdd(&g_bar[i], 1u) + 1u;
        unsigned target = ((v - 1u) / GRIDF_ + 1u) * GRIDF_;
        while (*((volatile unsigned*)&g_bar[i]) < target) __nanosleep(32);
        __threadfence();
    }
    __syncthreads();
}

// packed fp32x2 FMA (sm_103a; ptxas never emits this from C++)
__device__ __forceinline__ void ffma2(unsigned long long& acc,
                                      unsigned long long a,
                                      unsigned long long b)
{
    asm("fma.rn.f32x2 %0, %1, %2, %3;" : "=l"(acc) : "l"(a), "l"(b), "l"(acc));
}
__device__ __forceinline__ float unpack_sum(unsigned long long v)
{
    return __uint_as_float((unsigned)(v & 0xffffffffu))
         + __uint_as_float((unsigned)(v >> 32));
}

// ---------------------------------------------------------------------------
// Fused: [all blocks] stage fc_w tile -> [blocks 0-31] K1 per-batch
// (t-dots -> marginals -> pooled) -> grid barrier -> [all blocks] FC+tanh.
// grid = 192 x 512 threads, 2 blocks/SM co-resident (barrier-safe).
// ---------------------------------------------------------------------------
__global__ __launch_bounds__(512, 2) void fusedAll(
    const float* __restrict__ a1, const float* __restrict__ a2,
    const int*   __restrict__ m1, const int*   __restrict__ m2,
    const float* __restrict__ we_w,
    const float* __restrict__ fc_w, const float* __restrict__ fc_b,
    float* __restrict__ out)
{
    __shared__ float  sB[8 * D_];           // 24 KB fc_w tile
    __shared__ float  sw[D_];               // 3 KB
    __shared__ float  t1[L_], t2[L_];
    __shared__ float  rowsh[L_], colsh[L_];
    __shared__ float  ca[L_], cb[L_];
    __shared__ float  sinvd;
    __shared__ int    sl1, sl2;
    __shared__ float4 pp[2][D4_];           // 6 KB pooled partials

    const int tid  = threadIdx.x;
    const int lane = tid & 31;
    const int wid  = tid >> 5;              // 0..15
    const int bid  = blockIdx.x;
    const int o0   = bid * 8;

    // ---- stage fc_w tile (independent of K1 output) ----
    {
        const float4* src = (const float4*)(fc_w + (size_t)o0 * D_);
        float4*       dst = (float4*)sB;
        #pragma unroll
        for (int k = 0; k < 3; k++)
            dst[tid + 512*k] = src[tid + 512*k];
    }

    // ---- K1 on blocks 0..31 (batch b = bid) ----
    if (bid < B_) {
        const int b = bid;

        for (int i = tid; i < D_; i += 512) sw[i] = we_w[i];
        if (tid < L_) { rowsh[tid] = 0.f; colsh[tid] = 0.f; }
        if (wid == 0) {
            int s = m1[b*L_ + lane] + m1[b*L_ + lane + 32];
            #pragma unroll
            for (int o = 16; o; o >>= 1) s += __shfl_xor_sync(0xffffffffu, s, o);
            if (lane == 0) sl1 = s - 2;
        } else if (wid == 1) {
            int s = m2[b*L_ + lane] + m2[b*L_ + lane + 32];
            #pragma unroll
            for (int o = 16; o; o >>= 1) s += __shfl_xor_sync(0xffffffffu, s, o);
            if (lane == 0) sl2 = s - 2;
        }
        __syncthreads();

        const float4* base1v = (const float4*)(a1 + (size_t)b * L_ * D_);
        const float4* base2v = (const float4*)(a2 + (size_t)b * L_ * D_);
        const float4* swv    = (const float4*)sw;

        // t-phase: 128 tasks over 16 warps (8 each), 6-deep load batch
        #pragma unroll
        for (int it = 0; it < 8; it++) {
            const int task = wid + 16*it;
            const float4* row = (task < L_) ? (base1v + task*D4_)
                                            : (base2v + (task - L_)*D4_);
            float4 v[6];
            #pragma unroll
            for (int k = 0; k < 6; k++) v[k] = row[lane + 32*k];
            float s = 0.f;
            #pragma unroll
            for (int k = 0; k < 6; k++) {
                float4 wv = swv[lane + 32*k];
                s += v[k].x*wv.x + v[k].y*wv.y + v[k].z*wv.z + v[k].w*wv.w;
            }
            #pragma unroll
            for (int o = 16; o; o >>= 1) s += __shfl_xor_sync(0xffffffffu, s, o);
            if (lane == 0) { if (task < L_) t1[task] = s; else t2[task - L_] = s; }
        }
        __syncthreads();

        const int l1 = sl1, l2 = sl2;

        // marginals (no max-subtract: logits O(10), softmax shift-invariant;
        // padding exp(-1e7) underflows to 0)
        for (int i = wid; i < l1; i += 16) {
            const float ti = t1[i+1];
            float s = 0.f;
            #pragma unroll
            for (int base = 0; base < L_; base += 32) {
                int j = base + lane;
                if (j < l2) {
                    float we = ti - t2[j+1];
                    float m = (fabsf(we) < 1e-7f) ? -1e7f : we;
                    s += __expf(m);
                }
            }
            #pragma unroll
            for (int o = 16; o; o >>= 1) s += __shfl_xor_sync(0xffffffffu, s, o);
            if (lane == 0) rowsh[i] = s;
        }
        for (int j = wid; j < l2; j += 16) {
            const float tj = t2[j+1];
            float s = 0.f;
            #pragma unroll
            for (int base = 0; base < L_; base += 32) {
                int i = base + lane;
                if (i < l1) {
                    float we = t1[i+1] - tj;
                    float m = (fabsf(we) < 1e-7f) ? -1e7f : we;
                    s += __expf(m);
                }
            }
            #pragma unroll
            for (int o = 16; o; o >>= 1) s += __shfl_xor_sync(0xffffffffu, s, o);
            if (lane == 0) colsh[j] = s;
        }
        __syncthreads();

        if (wid == 0) {
            float s = rowsh[lane] + rowsh[lane + 32];
            #pragma unroll
            for (int o = 16; o; o >>= 1) s += __shfl_xor_sync(0xffffffffu, s, o);
            if (lane == 0) sinvd = 1.f / s;
        }
        __syncthreads();
        const float invd = sinvd;

        if (tid < L_) {
            ca[tid] = (tid >= 1 && tid - 1 < l1) ? rowsh[tid-1] * invd : 0.f;
        } else if (tid < 2*L_) {
            int j = tid - L_;
            cb[j] = (j >= 1 && j - 1 < l2) ? -colsh[j-1] * invd : 0.f;
        }
        __syncthreads();

        // pooled: 384 active threads; rg = tid/192 (rows rg*32..+31), c4 = tid%192
        if (tid < 2*D4_) {
            const int c4 = tid % D4_;
            const int rg = tid / D4_;
            float4 acc = make_float4(0.f, 0.f, 0.f, 0.f);
            #pragma unroll
            for (int k = 0; k < 32; k++) {
                const int r = rg*32 + k;
                const float c1 = ca[r];
                const float c2 = cb[r];
                float4 v1 = base1v[r*D4_ + c4];
                float4 v2 = base2v[r*D4_ + c4];
                acc.x += c1*v1.x + c2*v2.x;
                acc.y += c1*v1.y + c2*v2.y;
                acc.z += c1*v1.z + c2*v2.z;
                acc.w += c1*v1.w + c2*v2.w;
            }
            pp[rg][c4] = acc;
        }
        __syncthreads();

        if (tid < D4_) {
            float4 s0 = pp[0][tid];
            float4 s1 = pp[1][tid];
            ((float4*)g_pooled)[b*D4_ + tid] =
                make_float4(s0.x + s1.x, s0.y + s1.y, s0.z + s1.z, s0.w + s1.w);
        }
    }

    gsync(0);

    // ---- FC + tanh from staged smem tile (f32x2 packed) ----
    {
        const int b0 = wid * 2;
        const ulonglong2* poolu = (const ulonglong2*)g_pooled;
        ulonglong2 p[2][6];
        #pragma unroll
        for (int bb = 0; bb < 2; bb++)
            #pragma unroll
            for (int k = 0; k < 6; k++)
                p[bb][k] = poolu[(b0 + bb)*D4_ + lane + 32*k];

        const ulonglong2* sBu = (const ulonglong2*)sB;
        #pragma unroll
        for (int r = 0; r < 8; r++) {
            const int o = o0 + r;
            unsigned long long a0 = 0, a1v = 0;
            #pragma unroll
            for (int k = 0; k < 6; k++) {
                ulonglong2 w = sBu[r*D4_ + lane + 32*k];
                ffma2(a0, w.x, p[0][k].x); ffma2(a0, w.y, p[0][k].y);
                ffma2(a1v, w.x, p[1][k].x); ffma2(a1v, w.y, p[1][k].y);
            }
            float x0 = unpack_sum(a0);
            float x1 = unpack_sum(a1v);
            #pragma unroll
            for (int off = 16; off; off >>= 1) {
                x0 += __shfl_xor_sync(0xffffffffu, x0, off);
                x1 += __shfl_xor_sync(0xffffffffu, x1, off);
            }
            if (lane == 0) {
                const float bias = fc_b[o];
                out[(size_t)(b0+0)*OUTD_ + o] = tanhf(x0 + bias);
                out[(size_t)(b0+1)*OUTD_ + o] = tanhf(x1 + bias);
            }
        }
    }
}

extern "C" void kernel_launch(void* const* d_in, const int* in_sizes, int n_in,
                              void* d_out, int out_size)
{
    const float* a1   = (const float*)d_in[0];  // (B, L, D)
    const float* a2   = (const float*)d_in[1];  // (B, L, D)
    const int*   m1   = (const int*)  d_in[2];  // (B, L)
    const int*   m2   = (const int*)  d_in[3];  // (B, L)
    const float* we_w = (const float*)d_in[4];  // (1, D)
    const float* fc_w = (const float*)d_in[5];  // (2D, D)
    const float* fc_b = (const float*)d_in[6];  // (2D,)
    float* out = (float*)d_out;                 // (B, 2D)

    fusedAll<<<GRIDF_, 512>>>(a1, a2, m1, m2, we_w, fc_w, fc_b, out);
}

// round 16
// speedup vs baseline: 1.1511x; 1.1511x over previous
#include <cuda_runtime.h>
#include <math.h>

#define B_    32
#define L_    64
#define D_    768
#define LL_   (L_*L_)     // 4096
#define OUTD_ (2*D_)      // 1536
#define D4_   (D_/4)      // 192

// scratch
__device__ float g_pooled[B_ * D_];

// packed fp32x2 FMA (sm_103a; ptxas never emits this from C++)
__device__ __forceinline__ void ffma2(unsigned long long& acc,
                                      unsigned long long a,
                                      unsigned long long b)
{
    asm("fma.rn.f32x2 %0, %1, %2, %3;" : "=l"(acc) : "l"(a), "l"(b), "l"(acc));
}
__device__ __forceinline__ float unpack_sum(unsigned long long v)
{
    return __uint_as_float((unsigned)(v & 0xffffffffu))
         + __uint_as_float((unsigned)(v >> 32));
}

// ---------------------------------------------------------------------------
// K1: per-batch fused t-dots -> FACTORIZED masked-softmax marginals -> pooled.
// grid = 32 (one block per batch), block = 1024 (32 warps).
//
// Marginals: rowsum_i = exp(t1_i)*S2, colsum_j = exp(-t2_j)*S1, denom = S1*S2,
// with exact corrections for the (measure-zero) |t1_i - t2_j| < 1e-7 mask via
// an ALU-only pair scan + rare atomics. 128 exps instead of ~7200 (MUFU was
// the hidden 8us bottleneck).
// ---------------------------------------------------------------------------
__global__ __launch_bounds__(1024) void stageTMA(
    const float* __restrict__ a1, const float* __restrict__ a2,
    const int*   __restrict__ m1, const int*   __restrict__ m2,
    const float* __restrict__ we_w)
{
    __shared__ float  sw[D_];               // 3 KB
    __shared__ float  t1[L_], t2[L_];
    __shared__ float  e1[L_], e2m[L_];
    __shared__ float  rcorr[L_], ccorr[L_];
    __shared__ float  ca[L_], cb[L_];
    __shared__ float  sS1, sS2, sdcorr, sinvd;
    __shared__ int    sl1, sl2;
    __shared__ float4 pp[4][D4_];           // 12 KB pooled partials

    const int b    = blockIdx.x;
    const int tid  = threadIdx.x;
    const int lane = tid & 31;
    const int wid  = tid >> 5;              // 0..31

    if (tid < D_) sw[tid] = we_w[tid];
    if (tid < L_) { rcorr[tid] = 0.f; ccorr[tid] = 0.f; }
    if (tid == 0) sdcorr = 0.f;
    if (wid == 0) {
        int s = m1[b*L_ + lane] + m1[b*L_ + lane + 32];
        #pragma unroll
        for (int o = 16; o; o >>= 1) s += __shfl_xor_sync(0xffffffffu, s, o);
        if (lane == 0) sl1 = s - 2;
    } else if (wid == 1) {
        int s = m2[b*L_ + lane] + m2[b*L_ + lane + 32];
        #pragma unroll
        for (int o = 16; o; o >>= 1) s += __shfl_xor_sync(0xffffffffu, s, o);
        if (lane == 0) sl2 = s - 2;
    }
    __syncthreads();

    const float4* base1v = (const float4*)(a1 + (size_t)b * L_ * D_);
    const float4* base2v = (const float4*)(a2 + (size_t)b * L_ * D_);
    const float4* swv    = (const float4*)sw;

    // ---- Phase t: 128 row tasks over 32 warps (4 each, 2x2 pipelined) ----
    #pragma unroll
    for (int rr = 0; rr < 4; rr += 2) {
        const int taskA = wid + 32*rr;
        const int taskB = wid + 32*(rr+1);
        const float4* rowA = (taskA < L_) ? (base1v + taskA*D4_) : (base2v + (taskA-L_)*D4_);
        const float4* rowB = (taskB < L_) ? (base1v + taskB*D4_) : (base2v + (taskB-L_)*D4_);
        float4 va[6], vb[6];
        #pragma unroll
        for (int k = 0; k < 6; k++) va[k] = rowA[lane + 32*k];
        #pragma unroll
        for (int k = 0; k < 6; k++) vb[k] = rowB[lane + 32*k];
        float sA = 0.f, sB = 0.f;
        #pragma unroll
        for (int k = 0; k < 6; k++) {
            float4 wv = swv[lane + 32*k];
            sA += va[k].x*wv.x + va[k].y*wv.y + va[k].z*wv.z + va[k].w*wv.w;
            sB += vb[k].x*wv.x + vb[k].y*wv.y + vb[k].z*wv.z + vb[k].w*wv.w;
        }
        #pragma unroll
        for (int o = 16; o; o >>= 1) {
            sA += __shfl_xor_sync(0xffffffffu, sA, o);
            sB += __shfl_xor_sync(0xffffffffu, sB, o);
        }
        if (lane == 0) {
            if (taskA < L_) t1[taskA] = sA; else t2[taskA - L_] = sA;
            if (taskB < L_) t1[taskB] = sB; else t2[taskB - L_] = sB;
        }
    }
    __syncthreads();

    const int l1 = sl1, l2 = sl2;

    // ---- Factorized marginals: 128 exps total ----
    if (tid < L_) {
        e1[tid] = (tid < l1) ? __expf(t1[tid+1]) : 0.f;
    } else if (tid < 2*L_) {
        int j = tid - L_;
        e2m[j] = (j < l2) ? __expf(-t2[j+1]) : 0.f;
    }
    __syncthreads();

    if (wid == 0) {
        float s = e1[lane] + e1[lane + 32];
        #pragma unroll
        for (int o = 16; o; o >>= 1) s += __shfl_xor_sync(0xffffffffu, s, o);
        if (lane == 0) sS1 = s;
    } else if (wid == 1) {
        float s = e2m[lane] + e2m[lane + 32];
        #pragma unroll
        for (int o = 16; o; o >>= 1) s += __shfl_xor_sync(0xffffffffu, s, o);
        if (lane == 0) sS2 = s;
    }

    // ---- Mask-correction scan: ALU compares only; exp only on (rare) hits ----
    for (int kk = tid; kk < LL_; kk += 1024) {
        int i = kk >> 6;          // 0..63 (superset of valid i)
        int j = kk & 63;
        if (i < l1 && j < l2) {
            float we = t1[i+1] - t2[j+1];
            if (fabsf(we) < 1e-7f) {
                float ex = __expf(we);
                atomicAdd(&rcorr[i], ex);
                atomicAdd(&ccorr[j], ex);
                atomicAdd(&sdcorr, ex);
            }
        }
    }
    __syncthreads();

    const float S1 = sS1, S2 = sS2;
    if (tid == 0) sinvd = 1.f / (S1 * S2 - sdcorr);
    __syncthreads();
    const float invd = sinvd;

    if (tid < L_) {
        ca[tid] = (tid >= 1 && tid - 1 < l1)
                ? (e1[tid-1] * S2 - rcorr[tid-1]) * invd : 0.f;
    } else if (tid < 2*L_) {
        int j = tid - L_;
        cb[j] = (j >= 1 && j - 1 < l2)
              ? -(e2m[j-1] * S1 - ccorr[j-1]) * invd : 0.f;
    }
    __syncthreads();

    // ---- Pooled: 768 active threads; c4 = tid%192, row-group = tid/192 ----
    if (tid < 4*D4_) {
        const int c4 = tid % D4_;
        const int rg = tid / D4_;          // 0..3, rows rg*16 .. rg*16+15
        float4 acc = make_float4(0.f, 0.f, 0.f, 0.f);
        #pragma unroll
        for (int k = 0; k < 16; k++) {
            const int r = rg*16 + k;
            const float c1 = ca[r];
            const float c2 = cb[r];
            float4 v1 = base1v[r*D4_ + c4];
            float4 v2 = base2v[r*D4_ + c4];
            acc.x += c1*v1.x + c2*v2.x;
            acc.y += c1*v1.y + c2*v2.y;
            acc.z += c1*v1.z + c2*v2.z;
            acc.w += c1*v1.w + c2*v2.w;
        }
        pp[rg][c4] = acc;
    }
    __syncthreads();

    if (tid < D4_) {
        float4 s = pp[0][tid];
        #pragma unroll
        for (int k = 1; k < 4; k++) {
            float4 v = pp[k][tid];
            s.x += v.x; s.y += v.y; s.z += v.z; s.w += v.w;
        }
        ((float4*)g_pooled)[b*D4_ + tid] = s;
    }
}

// ---------------------------------------------------------------------------
// K2: out[b,o] = tanh( dot(pooled[b], fc_w[o]) + fc_b[o] )
// grid = 192, block = 512 (16 warps). One 8-row tile per block. (R14 config)
// ---------------------------------------------------------------------------
__global__ __launch_bounds__(512) void stageB(
    const float* __restrict__ fc_w, const float* __restrict__ fc_b,
    float* __restrict__ out)
{
    __shared__ float sB[8 * D_];   // 24 KB

    const int tid  = threadIdx.x;
    const int lane = tid & 31;
    const int wid  = tid >> 5;
    const int o0   = blockIdx.x * 8;
    const int b0   = wid * 2;

    {
        const float4* src = (const float4*)(fc_w + (size_t)o0 * D_);
        float4*       dst = (float4*)sB;
        #pragma unroll
        for (int k = 0; k < 3; k++)
            dst[tid + 512*k] = src[tid + 512*k];
    }

    const ulonglong2* poolu = (const ulonglong2*)g_pooled;
    ulonglong2 p[2][6];
    #pragma unroll
    for (int bb = 0; bb < 2; bb++)
        #pragma unroll
        for (int k = 0; k < 6; k++)
            p[bb][k] = poolu[(b0 + bb)*D4_ + lane + 32*k];

    __syncthreads();

    const ulonglong2* sBu = (const ulonglong2*)sB;
    #pragma unroll
    for (int r = 0; r < 8; r++) {
        const int o = o0 + r;
        unsigned long long a0 = 0, a1 = 0;
        #pragma unroll
        for (int k = 0; k < 6; k++) {
            ulonglong2 w = sBu[r*D4_ + lane + 32*k];
            ffma2(a0, w.x, p[0][k].x); ffma2(a0, w.y, p[0][k].y);
            ffma2(a1, w.x, p[1][k].x); ffma2(a1, w.y, p[1][k].y);
        }
        float x0 = unpack_sum(a0);
        float x1 = unpack_sum(a1);
        #pragma unroll
        for (int off = 16; off; off >>= 1) {
            x0 += __shfl_xor_sync(0xffffffffu, x0, off);
            x1 += __shfl_xor_sync(0xffffffffu, x1, off);
        }
        if (lane == 0) {
            const float bias = fc_b[o];
            out[(size_t)(b0+0)*OUTD_ + o] = tanhf(x0 + bias);
            out[(size_t)(b0+1)*OUTD_ + o] = tanhf(x1 + bias);
        }
    }
}

extern "C" void kernel_launch(void* const* d_in, const int* in_sizes, int n_in,
                              void* d_out, int out_size)
{
    const float* a1   = (const float*)d_in[0];  // (B, L, D)
    const float* a2   = (const float*)d_in[1];  // (B, L, D)
    const int*   m1   = (const int*)  d_in[2];  // (B, L)
    const int*   m2   = (const int*)  d_in[3];  // (B, L)
    const float* we_w = (const float*)d_in[4];  // (1, D)
    const float* fc_w = (const float*)d_in[5];  // (2D, D)
    const float* fc_b = (const float*)d_in[6];  // (2D,)
    float* out = (float*)d_out;                 // (B, 2D)

    stageTMA<<<B_, 1024>>>(a1, a2, m1, m2, we_w);
    stageB<<<OUTD_/8, 512>>>(fc_w, fc_b, out);
}

// round 17
// speedup vs baseline: 1.2758x; 1.1083x over previous
#include <cuda_runtime.h>
#include <math.h>

#define B_    32
#define L_    64
#define D_    768
#define LL_   (L_*L_)     // 4096
#define OUTD_ (2*D_)      // 1536
#define D4_   (D_/4)      // 192

// scratch
__device__ float g_pooled[B_ * D_];

// packed fp32x2 FMA (sm_103a; ptxas never emits this from C++)
__device__ __forceinline__ void ffma2(unsigned long long& acc,
                                      unsigned long long a,
                                      unsigned long long b)
{
    asm("fma.rn.f32x2 %0, %1, %2, %3;" : "=l"(acc) : "l"(a), "l"(b), "l"(acc));
}
__device__ __forceinline__ float unpack_sum(unsigned long long v)
{
    return __uint_as_float((unsigned)(v & 0xffffffffu))
         + __uint_as_float((unsigned)(v >> 32));
}

// ---------------------------------------------------------------------------
// K1: per-batch fused t-dots -> factorized masked-softmax marginals -> pooled.
// grid = 32 (one block per batch), block = 1024 (32 warps).
// Fires PDL trigger immediately: stageB may launch and stage fc_w concurrently.
// ---------------------------------------------------------------------------
__global__ __launch_bounds__(1024) void stageTMA(
    const float* __restrict__ a1, const float* __restrict__ a2,
    const int*   __restrict__ m1, const int*   __restrict__ m2,
    const float* __restrict__ we_w)
{
    // allow dependent (stageB) to launch right away; its griddepcontrol.wait
    // blocks before it reads g_pooled.
    asm volatile("griddepcontrol.launch_dependents;");

    __shared__ float  sw[D_];               // 3 KB
    __shared__ float  t1[L_], t2[L_];
    __shared__ float  e1[L_], e2m[L_];
    __shared__ float  rcorr[L_], ccorr[L_];
    __shared__ float  ca[L_], cb[L_];
    __shared__ float  sS1, sS2, sdcorr, sinvd;
    __shared__ int    sl1, sl2;
    __shared__ float4 pp[4][D4_];           // 12 KB pooled partials

    const int b    = blockIdx.x;
    const int tid  = threadIdx.x;
    const int lane = tid & 31;
    const int wid  = tid >> 5;              // 0..31

    if (tid < D_) sw[tid] = we_w[tid];
    if (tid < L_) { rcorr[tid] = 0.f; ccorr[tid] = 0.f; }
    if (tid == 0) sdcorr = 0.f;
    if (wid == 0) {
        int s = m1[b*L_ + lane] + m1[b*L_ + lane + 32];
        #pragma unroll
        for (int o = 16; o; o >>= 1) s += __shfl_xor_sync(0xffffffffu, s, o);
        if (lane == 0) sl1 = s - 2;
    } else if (wid == 1) {
        int s = m2[b*L_ + lane] + m2[b*L_ + lane + 32];
        #pragma unroll
        for (int o = 16; o; o >>= 1) s += __shfl_xor_sync(0xffffffffu, s, o);
        if (lane == 0) sl2 = s - 2;
    }
    __syncthreads();

    const float4* base1v = (const float4*)(a1 + (size_t)b * L_ * D_);
    const float4* base2v = (const float4*)(a2 + (size_t)b * L_ * D_);
    const float4* swv    = (const float4*)sw;

    // ---- Phase t: 128 row tasks over 32 warps (4 each, 2x2 pipelined) ----
    #pragma unroll
    for (int rr = 0; rr < 4; rr += 2) {
        const int taskA = wid + 32*rr;
        const int taskB = wid + 32*(rr+1);
        const float4* rowA = (taskA < L_) ? (base1v + taskA*D4_) : (base2v + (taskA-L_)*D4_);
        const float4* rowB = (taskB < L_) ? (base1v + taskB*D4_) : (base2v + (taskB-L_)*D4_);
        float4 va[6], vb[6];
        #pragma unroll
        for (int k = 0; k < 6; k++) va[k] = rowA[lane + 32*k];
        #pragma unroll
        for (int k = 0; k < 6; k++) vb[k] = rowB[lane + 32*k];
        float sA = 0.f, sB = 0.f;
        #pragma unroll
        for (int k = 0; k < 6; k++) {
            float4 wv = swv[lane + 32*k];
            sA += va[k].x*wv.x + va[k].y*wv.y + va[k].z*wv.z + va[k].w*wv.w;
            sB += vb[k].x*wv.x + vb[k].y*wv.y + vb[k].z*wv.z + vb[k].w*wv.w;
        }
        #pragma unroll
        for (int o = 16; o; o >>= 1) {
            sA += __shfl_xor_sync(0xffffffffu, sA, o);
            sB += __shfl_xor_sync(0xffffffffu, sB, o);
        }
        if (lane == 0) {
            if (taskA < L_) t1[taskA] = sA; else t2[taskA - L_] = sA;
            if (taskB < L_) t1[taskB] = sB; else t2[taskB - L_] = sB;
        }
    }
    __syncthreads();

    const int l1 = sl1, l2 = sl2;

    // ---- Factorized marginals: 128 exps total ----
    if (tid < L_) {
        e1[tid] = (tid < l1) ? __expf(t1[tid+1]) : 0.f;
    } else if (tid < 2*L_) {
        int j = tid - L_;
        e2m[j] = (j < l2) ? __expf(-t2[j+1]) : 0.f;
    }
    __syncthreads();

    if (wid == 0) {
        float s = e1[lane] + e1[lane + 32];
        #pragma unroll
        for (int o = 16; o; o >>= 1) s += __shfl_xor_sync(0xffffffffu, s, o);
        if (lane == 0) sS1 = s;
    } else if (wid == 1) {
        float s = e2m[lane] + e2m[lane + 32];
        #pragma unroll
        for (int o = 16; o; o >>= 1) s += __shfl_xor_sync(0xffffffffu, s, o);
        if (lane == 0) sS2 = s;
    }

    // ---- Mask-correction scan: ALU compares only; exp only on rare hits ----
    for (int kk = tid; kk < LL_; kk += 1024) {
        int i = kk >> 6;
        int j = kk & 63;
        if (i < l1 && j < l2) {
            float we = t1[i+1] - t2[j+1];
            if (fabsf(we) < 1e-7f) {
                float ex = __expf(we);
                atomicAdd(&rcorr[i], ex);
                atomicAdd(&ccorr[j], ex);
                atomicAdd(&sdcorr, ex);
            }
        }
    }
    __syncthreads();

    const float S1 = sS1, S2 = sS2;
    if (tid == 0) sinvd = 1.f / (S1 * S2 - sdcorr);
    __syncthreads();
    const float invd = sinvd;

    if (tid < L_) {
        ca[tid] = (tid >= 1 && tid - 1 < l1)
                ? (e1[tid-1] * S2 - rcorr[tid-1]) * invd : 0.f;
    } else if (tid < 2*L_) {
        int j = tid - L_;
        cb[j] = (j >= 1 && j - 1 < l2)
              ? -(e2m[j-1] * S1 - ccorr[j-1]) * invd : 0.f;
    }
    __syncthreads();

    // ---- Pooled: 768 active threads; c4 = tid%192, row-group = tid/192 ----
    if (tid < 4*D4_) {
        const int c4 = tid % D4_;
        const int rg = tid / D4_;
        float4 acc = make_float4(0.f, 0.f, 0.f, 0.f);
        #pragma unroll
        for (int k = 0; k < 16; k++) {
            const int r = rg*16 + k;
            const float c1 = ca[r];
            const float c2 = cb[r];
            float4 v1 = base1v[r*D4_ + c4];
            float4 v2 = base2v[r*D4_ + c4];
            acc.x += c1*v1.x + c2*v2.x;
            acc.y += c1*v1.y + c2*v2.y;
            acc.z += c1*v1.z + c2*v2.z;
            acc.w += c1*v1.w + c2*v2.w;
        }
        pp[rg][c4] = acc;
    }
    __syncthreads();

    if (tid < D4_) {
        float4 s = pp[0][tid];
        #pragma unroll
        for (int k = 1; k < 4; k++) {
            float4 v = pp[k][tid];
            s.x += v.x; s.y += v.y; s.z += v.z; s.w += v.w;
        }
        ((float4*)g_pooled)[b*D4_ + tid] = s;
    }
}

// ---------------------------------------------------------------------------
// K2: out[b,o] = tanh( dot(pooled[b], fc_w[o]) + fc_b[o] )
// grid = 192, block = 512. PDL secondary: stages fc_w concurrently with K1,
// then griddepcontrol.wait before consuming g_pooled.
// ---------------------------------------------------------------------------
__global__ __launch_bounds__(512) void stageB(
    const float* __restrict__ fc_w, const float* __restrict__ fc_b,
    float* __restrict__ out)
{
    __shared__ float sB[8 * D_];   // 24 KB

    const int tid  = threadIdx.x;
    const int lane = tid & 31;
    const int wid  = tid >> 5;
    const int o0   = blockIdx.x * 8;
    const int b0   = wid * 2;

    // stage fc_w tile (independent of K1's output) — overlaps with K1
    {
        const float4* src = (const float4*)(fc_w + (size_t)o0 * D_);
        float4*       dst = (float4*)sB;
        #pragma unroll
        for (int k = 0; k < 3; k++)
            dst[tid + 512*k] = src[tid + 512*k];
    }

    // wait for K1's writes (g_pooled) to be visible
    asm volatile("griddepcontrol.wait;");

    const ulonglong2* poolu = (const ulonglong2*)g_pooled;
    ulonglong2 p[2][6];
    #pragma unroll
    for (int bb = 0; bb < 2; bb++)
        #pragma unroll
        for (int k = 0; k < 6; k++)
            p[bb][k] = poolu[(b0 + bb)*D4_ + lane + 32*k];

    __syncthreads();

    const ulonglong2* sBu = (const ulonglong2*)sB;
    #pragma unroll
    for (int r = 0; r < 8; r++) {
        const int o = o0 + r;
        unsigned long long a0 = 0, a1 = 0;
        #pragma unroll
        for (int k = 0; k < 6; k++) {
            ulonglong2 w = sBu[r*D4_ + lane + 32*k];
            ffma2(a0, w.x, p[0][k].x); ffma2(a0, w.y, p[0][k].y);
            ffma2(a1, w.x, p[1][k].x); ffma2(a1, w.y, p[1][k].y);
        }
        float x0 = unpack_sum(a0);
        float x1 = unpack_sum(a1);
        #pragma unroll
        for (int off = 16; off; off >>= 1) {
            x0 += __shfl_xor_sync(0xffffffffu, x0, off);
            x1 += __shfl_xor_sync(0xffffffffu, x1, off);
        }
        if (lane == 0) {
            const float bias = fc_b[o];
            out[(size_t)(b0+0)*OUTD_ + o] = tanhf(x0 + bias);
            out[(size_t)(b0+1)*OUTD_ + o] = tanhf(x1 + bias);
        }
    }
}

extern "C" void kernel_launch(void* const* d_in, const int* in_sizes, int n_in,
                              void* d_out, int out_size)
{
    const float* a1   = (const float*)d_in[0];  // (B, L, D)
    const float* a2   = (const float*)d_in[1];  // (B, L, D)
    const int*   m1   = (const int*)  d_in[2];  // (B, L)
    const int*   m2   = (const int*)  d_in[3];  // (B, L)
    const float* we_w = (const float*)d_in[4];  // (1, D)
    const float* fc_w = (const float*)d_in[5];  // (2D, D)
    const float* fc_b = (const float*)d_in[6];  // (2D,)
    float* out = (float*)d_out;                 // (B, 2D)

    stageTMA<<<B_, 1024>>>(a1, a2, m1, m2, we_w);

    // stageB as PDL secondary: may launch/stage while K1 runs
    cudaLaunchConfig_t cfg = {};
    cfg.gridDim  = dim3(OUTD_/8);
    cfg.blockDim = dim3(512);
    cudaLaunchAttribute attr[1];
    attr[0].id = cudaLaunchAttributeProgrammaticStreamSerialization;
    attr[0].val.programmaticStreamSerializationAllowed = 1;
    cfg.attrs = attr;
    cfg.numAttrs = 1;
    cudaLaunchKernelEx(&cfg, stageB, fc_w, fc_b, out);
}